// round 15
// baseline (speedup 1.0000x reference)
#include <cuda_runtime.h>
#include <cstdint>
#include <math.h>

#define Nb 2
#define T  2048
#define H  256
#define NH 8
#define D  32
#define SCALE 17.677669529663689f

typedef unsigned long long u64;
typedef uint32_t u32;

__device__ __forceinline__ void fma2(u64& d, u64 a, u64 b) {
    asm("fma.rn.f32x2 %0, %1, %2, %0;" : "+l"(d) : "l"(a), "l"(b));
}
__device__ __forceinline__ u64 pack2(float x, float y) {
    u64 r; asm("mov.b64 %0, {%1, %2};" : "=l"(r) : "f"(x), "f"(y)); return r;
}
__device__ __forceinline__ float2 unpack2(u64 v) {
    float2 f; asm("mov.b64 {%0, %1}, %2;" : "=f"(f.x), "=f"(f.y) : "l"(v)); return f;
}
__device__ __forceinline__ u32 f16pack(float lo, float hi) {
    u32 r; asm("cvt.rn.f16x2.f32 %0, %1, %2;" : "=r"(r) : "f"(hi), "f"(lo)); return r;
}
/* hi/lo fp16 split of (x,y): hp + lp reconstructs to ~2^-22 */
__device__ __forceinline__ void f16split2(float x, float y, u32& hp, u32& lp) {
    hp = f16pack(x, y);
    float hx, hy;
    asm("{.reg .f16 l,h; mov.b32 {l,h}, %2; cvt.f32.f16 %0, l; cvt.f32.f16 %1, h;}"
        : "=f"(hx), "=f"(hy) : "r"(hp));
    lp = f16pack(x - hx, y - hy);
}
__device__ __forceinline__ u32 smem_u32(const void* p) {
    u32 a;
    asm("{ .reg .u64 t; cvta.to.shared.u64 t, %1; cvt.u32.u64 %0, t; }" : "=r"(a) : "l"(p));
    return a;
}
__device__ __forceinline__ void cpa16(u32 saddr, const void* g) {
    asm volatile("cp.async.cg.shared.global [%0], [%1], 16;" :: "r"(saddr), "l"(g));
}
#define CPA_COMMIT() asm volatile("cp.async.commit_group;" ::: "memory")
#define CPA_WAIT1()  asm volatile("cp.async.wait_group 1;"  ::: "memory")
#define CPA_WAIT0()  asm volatile("cp.async.wait_group 0;"  ::: "memory")
#define MMA16(c, a, b0, b1) \
    asm volatile("mma.sync.aligned.m16n8k16.row.col.f32.f16.f16.f32 " \
        "{%0,%1,%2,%3}, {%4,%5,%6,%7}, {%8,%9}, {%0,%1,%2,%3};" \
        : "+f"((c)[0]), "+f"((c)[1]), "+f"((c)[2]), "+f"((c)[3]) \
        : "r"((a)[0]), "r"((a)[1]), "r"((a)[2]), "r"((a)[3]), "r"(b0), "r"(b1))

/* packed K: [n*NH][32 tiles][8 grp][64 key] float4 {hi0,hi1,lo0,lo1} */
__device__ __align__(16) float4 g_Kp[Nb*NH*32*512];
/* packed V: [n*NH][32 tiles][16 grp][32 d] u64 {b0 f16x2, b1 f16x2}  */
__device__ __align__(16) u64 g_Vp[Nb*NH*32*512];
__device__ __align__(16) float g_Qh[Nb*NH*T*D];
__device__ __align__(16) float g_ctx[Nb*T*H];
__device__ float g_kbias[Nb*T];   /* 0 or -1e35 */
__device__ float g_qmask[Nb*T];

/* ------------------------------------------------------------------ */
__global__ void mask_kernel(const float* __restrict__ Q,
                            const float* __restrict__ K) {
    int row = blockIdx.x;
    const float* src = blockIdx.y ? K : Q;
    int t = threadIdx.x;
    float s = fabsf(src[row*H + t]) + fabsf(src[row*H + t + 128]);
    __shared__ float red[4];
    #pragma unroll
    for (int o = 16; o; o >>= 1) s += __shfl_xor_sync(0xffffffffu, s, o);
    if ((t & 31) == 0) red[t >> 5] = s;
    __syncthreads();
    if (t == 0) {
        float tot = red[0] + red[1] + red[2] + red[3];
        if (blockIdx.y) g_kbias[row] = (tot != 0.0f) ? 0.0f : -1e35f;
        else            g_qmask[row] = (tot != 0.0f) ? 1.0f : 0.0f;
    }
}

/* ------------------------------------------------------------------ */
__global__ void __launch_bounds__(256) proj_kernel(
        const float* __restrict__ Q, const float* __restrict__ K,
        const float* __restrict__ V,
        const float* __restrict__ Wq, const float* __restrict__ Wk,
        const float* __restrict__ Wv,
        const float* __restrict__ bq, const float* __restrict__ bk,
        const float* __restrict__ bv) {
    int sel = blockIdx.z;
    const float* X = (sel == 0) ? Q  : (sel == 1) ? K  : V;
    const float* W = (sel == 0) ? Wq : (sel == 1) ? Wk : Wv;
    const float* b = (sel == 0) ? bq : (sel == 1) ? bk : bv;
    int m0 = blockIdx.y * 64, n0 = blockIdx.x * 64;
    __shared__ __align__(16) float Xst[32][68];
    __shared__ __align__(16) float Wsh[32][68];
    int tid = threadIdx.x, ty = tid >> 4, tx = tid & 15;
    u64 acc2[4][2] = {};
    for (int k0 = 0; k0 < H; k0 += 32) {
        __syncthreads();
        #pragma unroll
        for (int it = 0; it < 8; ++it) {
            int e = tid + it * 256;
            int r = e >> 5, c = e & 31;
            Xst[c][r] = X[(m0 + r) * H + k0 + c];
            int r2 = e >> 6, c2 = e & 63;
            Wsh[r2][c2] = W[(k0 + r2) * H + n0 + c2];
        }
        __syncthreads();
        #pragma unroll
        for (int kk = 0; kk < 32; ++kk) {
            float4 a = *(const float4*)&Xst[kk][4 * ty];
            ulonglong2 bb = *(const ulonglong2*)&Wsh[kk][4 * tx];
            u64 a0 = pack2(a.x, a.x), a1 = pack2(a.y, a.y);
            u64 a2 = pack2(a.z, a.z), a3 = pack2(a.w, a.w);
            fma2(acc2[0][0], a0, bb.x); fma2(acc2[0][1], a0, bb.y);
            fma2(acc2[1][0], a1, bb.x); fma2(acc2[1][1], a1, bb.y);
            fma2(acc2[2][0], a2, bb.x); fma2(acc2[2][1], a2, bb.y);
            fma2(acc2[3][0], a3, bb.x); fma2(acc2[3][1], a3, bb.y);
        }
    }
    int c0 = n0 + 4 * tx, hh = c0 >> 5, d0 = c0 & 31;
    float b0 = b[c0+0], b1 = b[c0+1], b2 = b[c0+2], b3 = b[c0+3];
    #pragma unroll
    for (int i = 0; i < 4; ++i) {
        int m = m0 + 4 * ty + i, nn = m >> 11, tt = m & 2047;
        float2 lo = unpack2(acc2[i][0]), hi = unpack2(acc2[i][1]);
        float v0 = fmaxf(lo.x + b0, 0.0f), v1 = fmaxf(lo.y + b1, 0.0f);
        float v2 = fmaxf(hi.x + b2, 0.0f), v3 = fmaxf(hi.y + b3, 0.0f);
        int tile = tt >> 6, kk = tt & 63;
        size_t tbase = ((size_t)(nn * NH + hh) * 32 + tile) * 512;
        if (sel == 0) {
            *(float4*)&g_Qh[(((size_t)(nn * NH) + hh) * T + tt) * D + d0] =
                make_float4(v0, v1, v2, v3);
        } else if (sel == 1) {
            u32 h0, l0, h1, l1;
            f16split2(v0, v1, h0, l0);
            f16split2(v2, v3, h1, l1);
            int dp0 = d0 >> 1;
            #pragma unroll
            for (int p = 0; p < 2; ++p) {
                int dp = dp0 + p;
                int ks = dp >> 3, r = dp & 7, sB = r >> 2, tq = r & 3;
                u32* dst = (u32*)&g_Kp[tbase + (4*ks + tq) * 64 + kk];
                dst[sB]     = p ? h1 : h0;
                dst[sB + 2] = p ? l1 : l0;
            }
        } else {
            int kp = kk >> 1, sl = kk & 1;
            int r = kp & 7, sB = r >> 2, tq = r & 3, ks2 = kp >> 3;
            char* base = (char*)&g_Vp[tbase + ((4*ks2 + tq) * 32 + d0)]
                         + sB * 4 + sl * 2;
            unsigned short hv;
            asm("cvt.rn.f16.f32 %0, %1;" : "=h"(hv) : "f"(v0)); *(unsigned short*)(base)      = hv;
            asm("cvt.rn.f16.f32 %0, %1;" : "=h"(hv) : "f"(v1)); *(unsigned short*)(base + 8)  = hv;
            asm("cvt.rn.f16.f32 %0, %1;" : "=h"(hv) : "f"(v2)); *(unsigned short*)(base + 16) = hv;
            asm("cvt.rn.f16.f32 %0, %1;" : "=h"(hv) : "f"(v3)); *(unsigned short*)(base + 24) = hv;
        }
    }
}

/* ------------------------------------------------------------------ */
/* fp16-k16 flash attention: 3-term S (term-major, dep-chain broken), */
/* 1-term PV. Grid (16, NH, Nb), 128 thr (4 warps), warp = 32 q-rows. */
#define KOFF 0
#define VOFF 8448
#define BOFF 13056
#define BUFFB 13312
#define SMEM_BYTES (2 * BUFFB)

__global__ void __launch_bounds__(128, 3) attn_kernel() {
    extern __shared__ __align__(16) char dsm[];
    u32 sb = smem_u32(dsm);

    int tid = threadIdx.x, w = tid >> 5, lane = tid & 31;
    int g = lane >> 2, tq = lane & 3;
    int q0 = blockIdx.x * 128, hh = blockIdx.y, nn = blockIdx.z;
    const float* Qg = g_Qh + (size_t)(nn * NH + hh) * T * D;
    size_t tb = (size_t)(nn * NH + hh) * 32 * 512;

    u32 qh[2][2][4], ql[2][2][4];
    #pragma unroll
    for (int m = 0; m < 2; ++m) {
        int r0 = (q0 + 32 * w + 16 * m + g) * D;
        int r1 = r0 + 8 * D;
        #pragma unroll
        for (int ks = 0; ks < 2; ++ks) {
            float2 xa = *(const float2*)&Qg[r0 + 16*ks + 2*tq];
            float2 xb = *(const float2*)&Qg[r1 + 16*ks + 2*tq];
            float2 xc = *(const float2*)&Qg[r0 + 16*ks + 2*tq + 8];
            float2 xd = *(const float2*)&Qg[r1 + 16*ks + 2*tq + 8];
            f16split2(xa.x, xa.y, qh[m][ks][0], ql[m][ks][0]);
            f16split2(xb.x, xb.y, qh[m][ks][1], ql[m][ks][1]);
            f16split2(xc.x, xc.y, qh[m][ks][2], ql[m][ks][2]);
            f16split2(xd.x, xd.y, qh[m][ks][3], ql[m][ks][3]);
        }
    }
    float O[2][4][4];
    #pragma unroll
    for (int m = 0; m < 2; ++m)
        #pragma unroll
        for (int nf = 0; nf < 4; ++nf)
            #pragma unroll
            for (int c = 0; c < 4; ++c) O[m][nf][c] = 0.0f;
    float mrun[2][2] = {{-1e30f,-1e30f},{-1e30f,-1e30f}};
    float lrun[2][2] = {{0.f,0.f},{0.f,0.f}};

    auto prefetch = [&](int kt, int buf) {
        u32 base = sb + buf * BUFFB;
        const float4* gk = g_Kp + tb + (size_t)kt * 512;
        #pragma unroll
        for (int i = 0; i < 4; ++i) {
            int c = tid + i * 128;
            cpa16(base + KOFF + (c >> 6) * (66*16) + (c & 63) * 16, gk + c);
        }
        const u64* gv = g_Vp + tb + (size_t)kt * 512;
        #pragma unroll
        for (int i = 0; i < 2; ++i) {
            int c = tid + i * 128;
            cpa16(base + VOFF + (c >> 4) * 288 + (c & 15) * 16, gv + c * 2);
        }
        if (tid < 16)
            cpa16(base + BOFF + tid * 16, g_kbias + nn * T + kt * 64 + tid * 4);
        CPA_COMMIT();
    };

    prefetch(0, 0);

    for (int kt = 0; kt < T / 64; ++kt) {
        int cur = kt & 1;
        if (kt < T / 64 - 1) { prefetch(kt + 1, cur ^ 1); CPA_WAIT1(); }
        else CPA_WAIT0();
        __syncthreads();

        const float4* KP4 = (const float4*)(dsm + cur * BUFFB + KOFF);
        const u64*    VPu = (const u64*)   (dsm + cur * BUFFB + VOFF);
        const float*  bias_s = (const float*)(dsm + cur * BUFFB + BOFF);

        /* ---- S = Q K^T (3-term, j-pair x term-major: no C-dep chains) */
        float s[2][8][4];
        #pragma unroll
        for (int m = 0; m < 2; ++m)
            #pragma unroll
            for (int j = 0; j < 8; ++j)
                #pragma unroll
                for (int c = 0; c < 4; ++c) s[m][j][c] = 0.0f;
        #pragma unroll
        for (int ks = 0; ks < 2; ++ks) {
            #pragma unroll
            for (int jp = 0; jp < 4; ++jp) {
                int j0 = 2 * jp, j1 = 2 * jp + 1;
                float4 ka = KP4[(4*ks + tq) * 66 + 8*j0 + g];
                float4 kb = KP4[(4*ks + tq) * 66 + 8*j1 + g];
                u32 ah0 = __float_as_uint(ka.x), ah1 = __float_as_uint(ka.y);
                u32 al0 = __float_as_uint(ka.z), al1 = __float_as_uint(ka.w);
                u32 bh0 = __float_as_uint(kb.x), bh1 = __float_as_uint(kb.y);
                u32 bl0 = __float_as_uint(kb.z), bl1 = __float_as_uint(kb.w);
                /* term 1: qh x kh (4 independent MMAs) */
                MMA16(s[0][j0], qh[0][ks], ah0, ah1);
                MMA16(s[1][j0], qh[1][ks], ah0, ah1);
                MMA16(s[0][j1], qh[0][ks], bh0, bh1);
                MMA16(s[1][j1], qh[1][ks], bh0, bh1);
                /* term 2: ql x kh */
                MMA16(s[0][j0], ql[0][ks], ah0, ah1);
                MMA16(s[1][j0], ql[1][ks], ah0, ah1);
                MMA16(s[0][j1], ql[0][ks], bh0, bh1);
                MMA16(s[1][j1], ql[1][ks], bh0, bh1);
                /* term 3: qh x kl */
                MMA16(s[0][j0], qh[0][ks], al0, al1);
                MMA16(s[1][j0], qh[1][ks], al0, al1);
                MMA16(s[0][j1], qh[0][ks], bl0, bl1);
                MMA16(s[1][j1], qh[1][ks], bl0, bl1);
            }
        }

        /* ---- softmax over 64 keys ---- */
        float2 bb[8];
        #pragma unroll
        for (int j = 0; j < 8; ++j)
            bb[j] = *(const float2*)&bias_s[8*j + 2*tq];
        #pragma unroll
        for (int m = 0; m < 2; ++m)
            #pragma unroll
            for (int rg = 0; rg < 2; ++rg) {
                float zv[16];
                #pragma unroll
                for (int j = 0; j < 8; ++j) {
                    zv[2*j]   = fmaf(s[m][j][2*rg],   SCALE, bb[j].x);
                    zv[2*j+1] = fmaf(s[m][j][2*rg+1], SCALE, bb[j].y);
                }
                float m0 = fmaxf(zv[0], zv[1]),  m1 = fmaxf(zv[2], zv[3]);
                float m2 = fmaxf(zv[4], zv[5]),  m3 = fmaxf(zv[6], zv[7]);
                float m4 = fmaxf(zv[8], zv[9]),  m5 = fmaxf(zv[10], zv[11]);
                float m6 = fmaxf(zv[12], zv[13]), m7 = fmaxf(zv[14], zv[15]);
                float mx = fmaxf(fmaxf(fmaxf(m0, m1), fmaxf(m2, m3)),
                                 fmaxf(fmaxf(m4, m5), fmaxf(m6, m7)));
                mx = fmaxf(mx, __shfl_xor_sync(0xffffffffu, mx, 1));
                mx = fmaxf(mx, __shfl_xor_sync(0xffffffffu, mx, 2));
                float mn = fmaxf(mrun[m][rg], mx);
                float fr = __expf(mrun[m][rg] - mn);
                mrun[m][rg] = mn;
                float sum = 0.0f;
                #pragma unroll
                for (int j = 0; j < 8; ++j) {
                    float p0 = __expf(zv[2*j]   - mn);
                    float p1 = __expf(zv[2*j+1] - mn);
                    sum += p0 + p1;
                    s[m][j][2*rg] = p0; s[m][j][2*rg+1] = p1;
                }
                sum += __shfl_xor_sync(0xffffffffu, sum, 1);
                sum += __shfl_xor_sync(0xffffffffu, sum, 2);
                lrun[m][rg] = lrun[m][rg] * fr + sum;
                #pragma unroll
                for (int nf = 0; nf < 4; ++nf) {
                    O[m][nf][2*rg]   *= fr;
                    O[m][nf][2*rg+1] *= fr;
                }
            }
        /* drop key T-1 from ctx (still in softmax denom) */
        if (kt == T / 64 - 1 && tq == 3) {
            s[0][7][1] = 0.0f; s[0][7][3] = 0.0f;
            s[1][7][1] = 0.0f; s[1][7][3] = 0.0f;
        }

        /* ---- O += P V (1-term: ph x vh), P packed lane-locally ---- */
        #pragma unroll
        for (int ks2 = 0; ks2 < 4; ++ks2) {
            u32 ph[2][4];
            #pragma unroll
            for (int m = 0; m < 2; ++m) {
                ph[m][0] = f16pack(s[m][2*ks2][0],   s[m][2*ks2][1]);
                ph[m][1] = f16pack(s[m][2*ks2][2],   s[m][2*ks2][3]);
                ph[m][2] = f16pack(s[m][2*ks2+1][0], s[m][2*ks2+1][1]);
                ph[m][3] = f16pack(s[m][2*ks2+1][2], s[m][2*ks2+1][3]);
            }
            #pragma unroll
            for (int nf = 0; nf < 4; ++nf) {
                u64 vv = VPu[(4*ks2 + tq) * 36 + 8*nf + g];
                u32 v0 = (u32)vv, v1 = (u32)(vv >> 32);
                #pragma unroll
                for (int m = 0; m < 2; ++m)
                    MMA16(O[m][nf], ph[m], v0, v1);
            }
        }
        __syncthreads();
    }

    /* ---- epilogue ---- */
    #pragma unroll
    for (int m = 0; m < 2; ++m)
        #pragma unroll
        for (int rg = 0; rg < 2; ++rg) {
            int row = q0 + 32 * w + 16 * m + 8 * rg + g;
            float inv = g_qmask[nn * T + row] / lrun[m][rg];
            float* dst = &g_ctx[(size_t)(nn * T + row) * H + hh * D];
            #pragma unroll
            for (int nf = 0; nf < 4; ++nf)
                *(float2*)&dst[8*nf + 2*tq] =
                    make_float2(O[m][nf][2*rg] * inv, O[m][nf][2*rg+1] * inv);
        }
}

/* ------------------------------------------------------------------ */
__global__ void __launch_bounds__(256) ln_kernel(
        const float* __restrict__ gamma, const float* __restrict__ beta,
        float* __restrict__ out, float* __restrict__ wout) {
    int row = blockIdx.x, t = threadIdx.x;
    float x = g_ctx[(size_t)row * H + t];
    __shared__ float rs[8], rq[8];
    float s = x, q = x * x;
    #pragma unroll
    for (int o = 16; o; o >>= 1) {
        s += __shfl_xor_sync(0xffffffffu, s, o);
        q += __shfl_xor_sync(0xffffffffu, q, o);
    }
    if ((t & 31) == 0) { rs[t >> 5] = s; rq[t >> 5] = q; }
    __syncthreads();
    float ts = 0.0f, tq = 0.0f;
    #pragma unroll
    for (int i = 0; i < 8; ++i) { ts += rs[i]; tq += rq[i]; }
    float mu = ts * (1.0f / H);
    float var = tq * (1.0f / H) - mu * mu;
    float inv = rsqrtf(var + 1e-5f);
    out[(size_t)row * H + t] = (x - mu) * inv * gamma[t] + beta[t];
    if (t == 0) wout[row] = g_qmask[row] * (1.0f / (float)T);
}

/* ------------------------------------------------------------------ */
extern "C" void kernel_launch(void* const* d_in, const int* in_sizes, int n_in,
                              void* d_out, int out_size) {
    const float* Q  = (const float*)d_in[0];
    const float* K  = (const float*)d_in[1];
    const float* V  = (const float*)d_in[2];
    const float* Wq = (const float*)d_in[3];
    const float* bq = (const float*)d_in[4];
    const float* Wk = (const float*)d_in[5];
    const float* bk = (const float*)d_in[6];
    const float* Wv = (const float*)d_in[7];
    const float* bv = (const float*)d_in[8];
    const float* gamma = (const float*)d_in[9];
    const float* beta  = (const float*)d_in[10];

    float* out  = (float*)d_out;
    float* wout = out + (out_size - Nb * T);

    cudaFuncSetAttribute(attn_kernel,
                         cudaFuncAttributeMaxDynamicSharedMemorySize, SMEM_BYTES);

    mask_kernel<<<dim3(Nb * T, 2), 128>>>(Q, K);
    proj_kernel<<<dim3(H / 64, (Nb * T) / 64, 3), 256>>>(Q, K, V,
                                                         Wq, Wk, Wv,
                                                         bq, bk, bv);
    attn_kernel<<<dim3(T / 128, NH, Nb), 128, SMEM_BYTES>>>();
    ln_kernel<<<Nb * T, 256>>>(gamma, beta, out, wout);
}

// round 16
// speedup vs baseline: 1.0191x; 1.0191x over previous
#include <cuda_runtime.h>
#include <cstdint>
#include <math.h>

#define Nb 2
#define T  2048
#define H  256
#define NH 8
#define D  32
#define SCALE 17.677669529663689f

typedef unsigned long long u64;
typedef uint32_t u32;

__device__ __forceinline__ void fma2(u64& d, u64 a, u64 b) {
    asm("fma.rn.f32x2 %0, %1, %2, %0;" : "+l"(d) : "l"(a), "l"(b));
}
__device__ __forceinline__ u64 pack2(float x, float y) {
    u64 r; asm("mov.b64 %0, {%1, %2};" : "=l"(r) : "f"(x), "f"(y)); return r;
}
__device__ __forceinline__ float2 unpack2(u64 v) {
    float2 f; asm("mov.b64 {%0, %1}, %2;" : "=f"(f.x), "=f"(f.y) : "l"(v)); return f;
}
__device__ __forceinline__ u32 f16pack(float lo, float hi) {
    u32 r; asm("cvt.rn.f16x2.f32 %0, %1, %2;" : "=r"(r) : "f"(hi), "f"(lo)); return r;
}
/* hi/lo fp16 split of (x,y): hp + lp reconstructs to ~2^-22 */
__device__ __forceinline__ void f16split2(float x, float y, u32& hp, u32& lp) {
    hp = f16pack(x, y);
    float hx, hy;
    asm("{.reg .f16 l,h; mov.b32 {l,h}, %2; cvt.f32.f16 %0, l; cvt.f32.f16 %1, h;}"
        : "=f"(hx), "=f"(hy) : "r"(hp));
    lp = f16pack(x - hx, y - hy);
}
__device__ __forceinline__ u32 smem_u32(const void* p) {
    u32 a;
    asm("{ .reg .u64 t; cvta.to.shared.u64 t, %1; cvt.u32.u64 %0, t; }" : "=r"(a) : "l"(p));
    return a;
}
__device__ __forceinline__ void cpa16(u32 saddr, const void* g) {
    asm volatile("cp.async.cg.shared.global [%0], [%1], 16;" :: "r"(saddr), "l"(g));
}
#define CPA_COMMIT() asm volatile("cp.async.commit_group;" ::: "memory")
#define CPA_WAIT1()  asm volatile("cp.async.wait_group 1;"  ::: "memory")
#define CPA_WAIT0()  asm volatile("cp.async.wait_group 0;"  ::: "memory")
#define MMA16(c, a, b0, b1) \
    asm volatile("mma.sync.aligned.m16n8k16.row.col.f32.f16.f16.f32 " \
        "{%0,%1,%2,%3}, {%4,%5,%6,%7}, {%8,%9}, {%0,%1,%2,%3};" \
        : "+f"((c)[0]), "+f"((c)[1]), "+f"((c)[2]), "+f"((c)[3]) \
        : "r"((a)[0]), "r"((a)[1]), "r"((a)[2]), "r"((a)[3]), "r"(b0), "r"(b1))

/* packed K: [n*NH][32 tiles][8 grp][64 key] float4 {hi0,hi1,lo0,lo1} */
__device__ __align__(16) float4 g_Kp[Nb*NH*32*512];
/* packed V: [n*NH][32 tiles][16 grp][32 d] u64 {b0 f16x2, b1 f16x2}  */
__device__ __align__(16) u64 g_Vp[Nb*NH*32*512];
__device__ __align__(16) float g_Qh[Nb*NH*T*D];
__device__ __align__(16) float g_ctx[Nb*T*H];
__device__ float g_kbias[Nb*T];   /* 0 or -1e35 */
__device__ float g_qmask[Nb*T];

/* ------------------------------------------------------------------ */
__global__ void mask_kernel(const float* __restrict__ Q,
                            const float* __restrict__ K) {
    int row = blockIdx.x;
    const float* src = blockIdx.y ? K : Q;
    int t = threadIdx.x;
    float s = fabsf(src[row*H + t]) + fabsf(src[row*H + t + 128]);
    __shared__ float red[4];
    #pragma unroll
    for (int o = 16; o; o >>= 1) s += __shfl_xor_sync(0xffffffffu, s, o);
    if ((t & 31) == 0) red[t >> 5] = s;
    __syncthreads();
    if (t == 0) {
        float tot = red[0] + red[1] + red[2] + red[3];
        if (blockIdx.y) g_kbias[row] = (tot != 0.0f) ? 0.0f : -1e35f;
        else            g_qmask[row] = (tot != 0.0f) ? 1.0f : 0.0f;
    }
}

/* ------------------------------------------------------------------ */
/* Projection, pipelined: W via cp.async dbl-buffer, X reg-staged.    */
__global__ void __launch_bounds__(256) proj_kernel(
        const float* __restrict__ Q, const float* __restrict__ K,
        const float* __restrict__ V,
        const float* __restrict__ Wq, const float* __restrict__ Wk,
        const float* __restrict__ Wv,
        const float* __restrict__ bq, const float* __restrict__ bk,
        const float* __restrict__ bv) {
    int sel = blockIdx.z;
    const float* X = (sel == 0) ? Q  : (sel == 1) ? K  : V;
    const float* W = (sel == 0) ? Wq : (sel == 1) ? Wk : Wv;
    const float* b = (sel == 0) ? bq : (sel == 1) ? bk : bv;
    int m0 = blockIdx.y * 64, n0 = blockIdx.x * 64;
    __shared__ __align__(16) float Xst[2][32][68];
    __shared__ __align__(16) float Wsh[2][32][68];
    int tid = threadIdx.x, ty = tid >> 4, tx = tid & 15;
    u32 wbase = smem_u32(&Wsh[0][0][0]);

    float xr[8];
    u64 acc2[4][2] = {};

    /* prologue: W step0 via cp.async; X step0 direct */
    #pragma unroll
    for (int i = 0; i < 2; ++i) {
        int idx = tid + i * 256;
        int r2 = idx >> 4, ch = idx & 15;
        cpa16(wbase + r2 * (68 * 4) + ch * 16, W + r2 * H + n0 + ch * 4);
    }
    CPA_COMMIT();
    #pragma unroll
    for (int it = 0; it < 8; ++it) {
        int e = tid + it * 256;
        xr[it] = X[(m0 + (e >> 5)) * H + (e & 31)];
    }
    #pragma unroll
    for (int it = 0; it < 8; ++it) {
        int e = tid + it * 256;
        Xst[0][e & 31][e >> 5] = xr[it];
    }

    for (int ksamp = 0; ksamp < 8; ++ksamp) {
        int cur = ksamp & 1;
        CPA_WAIT0();
        __syncthreads();
        if (ksamp < 7) {
            int k1 = (ksamp + 1) * 32;
            #pragma unroll
            for (int i = 0; i < 2; ++i) {
                int idx = tid + i * 256;
                int r2 = idx >> 4, ch = idx & 15;
                cpa16(wbase + (cur ^ 1) * (32 * 68 * 4) + r2 * (68 * 4) + ch * 16,
                      W + (k1 + r2) * H + n0 + ch * 4);
            }
            CPA_COMMIT();
            #pragma unroll
            for (int it = 0; it < 8; ++it) {
                int e = tid + it * 256;
                xr[it] = X[(m0 + (e >> 5)) * H + k1 + (e & 31)];
            }
        }
        #pragma unroll
        for (int kk = 0; kk < 32; ++kk) {
            float4 a = *(const float4*)&Xst[cur][kk][4 * ty];
            ulonglong2 bb = *(const ulonglong2*)&Wsh[cur][kk][4 * tx];
            u64 a0 = pack2(a.x, a.x), a1 = pack2(a.y, a.y);
            u64 a2 = pack2(a.z, a.z), a3 = pack2(a.w, a.w);
            fma2(acc2[0][0], a0, bb.x); fma2(acc2[0][1], a0, bb.y);
            fma2(acc2[1][0], a1, bb.x); fma2(acc2[1][1], a1, bb.y);
            fma2(acc2[2][0], a2, bb.x); fma2(acc2[2][1], a2, bb.y);
            fma2(acc2[3][0], a3, bb.x); fma2(acc2[3][1], a3, bb.y);
        }
        if (ksamp < 7) {
            #pragma unroll
            for (int it = 0; it < 8; ++it) {
                int e = tid + it * 256;
                Xst[cur ^ 1][e & 31][e >> 5] = xr[it];
            }
        }
    }

    int c0 = n0 + 4 * tx, hh = c0 >> 5, d0 = c0 & 31;
    float b0 = b[c0+0], b1 = b[c0+1], b2 = b[c0+2], b3 = b[c0+3];
    #pragma unroll
    for (int i = 0; i < 4; ++i) {
        int m = m0 + 4 * ty + i, nn = m >> 11, tt = m & 2047;
        float2 lo = unpack2(acc2[i][0]), hi = unpack2(acc2[i][1]);
        float v0 = fmaxf(lo.x + b0, 0.0f), v1 = fmaxf(lo.y + b1, 0.0f);
        float v2 = fmaxf(hi.x + b2, 0.0f), v3 = fmaxf(hi.y + b3, 0.0f);
        int tile = tt >> 6, kk = tt & 63;
        size_t tbase = ((size_t)(nn * NH + hh) * 32 + tile) * 512;
        if (sel == 0) {
            *(float4*)&g_Qh[(((size_t)(nn * NH) + hh) * T + tt) * D + d0] =
                make_float4(v0, v1, v2, v3);
        } else if (sel == 1) {
            u32 h0, l0, h1, l1;
            f16split2(v0, v1, h0, l0);
            f16split2(v2, v3, h1, l1);
            int dp0 = d0 >> 1;
            #pragma unroll
            for (int p = 0; p < 2; ++p) {
                int dp = dp0 + p;
                int ks = dp >> 3, r = dp & 7, sB = r >> 2, tq = r & 3;
                u32* dst = (u32*)&g_Kp[tbase + (4*ks + tq) * 64 + kk];
                dst[sB]     = p ? h1 : h0;
                dst[sB + 2] = p ? l1 : l0;
            }
        } else {
            int kp = kk >> 1, sl = kk & 1;
            int r = kp & 7, sB = r >> 2, tq = r & 3, ks2 = kp >> 3;
            char* base = (char*)&g_Vp[tbase + ((4*ks2 + tq) * 32 + d0)]
                         + sB * 4 + sl * 2;
            unsigned short hv;
            asm("cvt.rn.f16.f32 %0, %1;" : "=h"(hv) : "f"(v0)); *(unsigned short*)(base)      = hv;
            asm("cvt.rn.f16.f32 %0, %1;" : "=h"(hv) : "f"(v1)); *(unsigned short*)(base + 8)  = hv;
            asm("cvt.rn.f16.f32 %0, %1;" : "=h"(hv) : "f"(v2)); *(unsigned short*)(base + 16) = hv;
            asm("cvt.rn.f16.f32 %0, %1;" : "=h"(hv) : "f"(v3)); *(unsigned short*)(base + 24) = hv;
        }
    }
}

/* ------------------------------------------------------------------ */
/* fp16-k16 flash attention: 3-term S, 1-term PV. Grid (16, NH, Nb),  */
/* 128 thr (4 warps), warp = 32 q-rows (m=2).                         */
#define KOFF 0
#define VOFF 8448
#define BOFF 13056
#define BUFFB 13312
#define SMEM_BYTES (2 * BUFFB)

__global__ void __launch_bounds__(128, 3) attn_kernel() {
    extern __shared__ __align__(16) char dsm[];
    u32 sb = smem_u32(dsm);

    int tid = threadIdx.x, w = tid >> 5, lane = tid & 31;
    int g = lane >> 2, tq = lane & 3;
    int q0 = blockIdx.x * 128, hh = blockIdx.y, nn = blockIdx.z;
    const float* Qg = g_Qh + (size_t)(nn * NH + hh) * T * D;
    size_t tb = (size_t)(nn * NH + hh) * 32 * 512;

    u32 qh[2][2][4], ql[2][2][4];
    #pragma unroll
    for (int m = 0; m < 2; ++m) {
        int r0 = (q0 + 32 * w + 16 * m + g) * D;
        int r1 = r0 + 8 * D;
        #pragma unroll
        for (int ks = 0; ks < 2; ++ks) {
            float2 xa = *(const float2*)&Qg[r0 + 16*ks + 2*tq];
            float2 xb = *(const float2*)&Qg[r1 + 16*ks + 2*tq];
            float2 xc = *(const float2*)&Qg[r0 + 16*ks + 2*tq + 8];
            float2 xd = *(const float2*)&Qg[r1 + 16*ks + 2*tq + 8];
            f16split2(xa.x, xa.y, qh[m][ks][0], ql[m][ks][0]);
            f16split2(xb.x, xb.y, qh[m][ks][1], ql[m][ks][1]);
            f16split2(xc.x, xc.y, qh[m][ks][2], ql[m][ks][2]);
            f16split2(xd.x, xd.y, qh[m][ks][3], ql[m][ks][3]);
        }
    }
    float O[2][4][4];
    #pragma unroll
    for (int m = 0; m < 2; ++m)
        #pragma unroll
        for (int nf = 0; nf < 4; ++nf)
            #pragma unroll
            for (int c = 0; c < 4; ++c) O[m][nf][c] = 0.0f;
    float mrun[2][2] = {{-1e30f,-1e30f},{-1e30f,-1e30f}};
    float lrun[2][2] = {{0.f,0.f},{0.f,0.f}};

    auto prefetch = [&](int kt, int buf) {
        u32 base = sb + buf * BUFFB;
        const float4* gk = g_Kp + tb + (size_t)kt * 512;
        #pragma unroll
        for (int i = 0; i < 4; ++i) {
            int c = tid + i * 128;
            cpa16(base + KOFF + (c >> 6) * (66*16) + (c & 63) * 16, gk + c);
        }
        const u64* gv = g_Vp + tb + (size_t)kt * 512;
        #pragma unroll
        for (int i = 0; i < 2; ++i) {
            int c = tid + i * 128;
            cpa16(base + VOFF + (c >> 4) * 288 + (c & 15) * 16, gv + c * 2);
        }
        if (tid < 16)
            cpa16(base + BOFF + tid * 16, g_kbias + nn * T + kt * 64 + tid * 4);
        CPA_COMMIT();
    };

    prefetch(0, 0);

    for (int kt = 0; kt < T / 64; ++kt) {
        int cur = kt & 1;
        if (kt < T / 64 - 1) { prefetch(kt + 1, cur ^ 1); CPA_WAIT1(); }
        else CPA_WAIT0();
        __syncthreads();

        const float4* KP4 = (const float4*)(dsm + cur * BUFFB + KOFF);
        const u64*    VPu = (const u64*)   (dsm + cur * BUFFB + VOFF);
        const float*  bias_s = (const float*)(dsm + cur * BUFFB + BOFF);

        /* ---- S = Q K^T (3-term fp16 k16), full 64-key tile ---- */
        float s[2][8][4];
        #pragma unroll
        for (int m = 0; m < 2; ++m)
            #pragma unroll
            for (int j = 0; j < 8; ++j)
                #pragma unroll
                for (int c = 0; c < 4; ++c) s[m][j][c] = 0.0f;
        #pragma unroll
        for (int ks = 0; ks < 2; ++ks) {
            #pragma unroll
            for (int j = 0; j < 8; ++j) {
                float4 kf = KP4[(4*ks + tq) * 66 + 8*j + g];
                u32 bh0 = __float_as_uint(kf.x), bh1 = __float_as_uint(kf.y);
                u32 bl0 = __float_as_uint(kf.z), bl1 = __float_as_uint(kf.w);
                #pragma unroll
                for (int m = 0; m < 2; ++m) {
                    MMA16(s[m][j], qh[m][ks], bh0, bh1);
                    MMA16(s[m][j], ql[m][ks], bh0, bh1);
                    MMA16(s[m][j], qh[m][ks], bl0, bl1);
                }
            }
        }

        /* ---- softmax over 64 keys ---- */
        float2 bb[8];
        #pragma unroll
        for (int j = 0; j < 8; ++j)
            bb[j] = *(const float2*)&bias_s[8*j + 2*tq];
        #pragma unroll
        for (int m = 0; m < 2; ++m)
            #pragma unroll
            for (int rg = 0; rg < 2; ++rg) {
                float zv[16];
                #pragma unroll
                for (int j = 0; j < 8; ++j) {
                    zv[2*j]   = fmaf(s[m][j][2*rg],   SCALE, bb[j].x);
                    zv[2*j+1] = fmaf(s[m][j][2*rg+1], SCALE, bb[j].y);
                }
                float m0 = fmaxf(zv[0], zv[1]),  m1 = fmaxf(zv[2], zv[3]);
                float m2 = fmaxf(zv[4], zv[5]),  m3 = fmaxf(zv[6], zv[7]);
                float m4 = fmaxf(zv[8], zv[9]),  m5 = fmaxf(zv[10], zv[11]);
                float m6 = fmaxf(zv[12], zv[13]), m7 = fmaxf(zv[14], zv[15]);
                float mx = fmaxf(fmaxf(fmaxf(m0, m1), fmaxf(m2, m3)),
                                 fmaxf(fmaxf(m4, m5), fmaxf(m6, m7)));
                mx = fmaxf(mx, __shfl_xor_sync(0xffffffffu, mx, 1));
                mx = fmaxf(mx, __shfl_xor_sync(0xffffffffu, mx, 2));
                float mn = fmaxf(mrun[m][rg], mx);
                float fr = __expf(mrun[m][rg] - mn);
                mrun[m][rg] = mn;
                float sum = 0.0f;
                #pragma unroll
                for (int j = 0; j < 8; ++j) {
                    float p0 = __expf(zv[2*j]   - mn);
                    float p1 = __expf(zv[2*j+1] - mn);
                    sum += p0 + p1;
                    s[m][j][2*rg] = p0; s[m][j][2*rg+1] = p1;
                }
                sum += __shfl_xor_sync(0xffffffffu, sum, 1);
                sum += __shfl_xor_sync(0xffffffffu, sum, 2);
                lrun[m][rg] = lrun[m][rg] * fr + sum;
                #pragma unroll
                for (int nf = 0; nf < 4; ++nf) {
                    O[m][nf][2*rg]   *= fr;
                    O[m][nf][2*rg+1] *= fr;
                }
            }
        /* drop key T-1 from ctx (still in softmax denom) */
        if (kt == T / 64 - 1 && tq == 3) {
            s[0][7][1] = 0.0f; s[0][7][3] = 0.0f;
            s[1][7][1] = 0.0f; s[1][7][3] = 0.0f;
        }

        /* ---- O += P V (1-term: ph x vh), P packed lane-locally ---- */
        #pragma unroll
        for (int ks2 = 0; ks2 < 4; ++ks2) {
            u32 ph[2][4];
            #pragma unroll
            for (int m = 0; m < 2; ++m) {
                ph[m][0] = f16pack(s[m][2*ks2][0],   s[m][2*ks2][1]);
                ph[m][1] = f16pack(s[m][2*ks2][2],   s[m][2*ks2][3]);
                ph[m][2] = f16pack(s[m][2*ks2+1][0], s[m][2*ks2+1][1]);
                ph[m][3] = f16pack(s[m][2*ks2+1][2], s[m][2*ks2+1][3]);
            }
            #pragma unroll
            for (int nf = 0; nf < 4; ++nf) {
                u64 vv = VPu[(4*ks2 + tq) * 36 + 8*nf + g];
                u32 v0 = (u32)vv, v1 = (u32)(vv >> 32);
                #pragma unroll
                for (int m = 0; m < 2; ++m)
                    MMA16(O[m][nf], ph[m], v0, v1);
            }
        }
        __syncthreads();
    }

    /* ---- epilogue ---- */
    #pragma unroll
    for (int m = 0; m < 2; ++m)
        #pragma unroll
        for (int rg = 0; rg < 2; ++rg) {
            int row = q0 + 32 * w + 16 * m + 8 * rg + g;
            float inv = g_qmask[nn * T + row] / lrun[m][rg];
            float* dst = &g_ctx[(size_t)(nn * T + row) * H + hh * D];
            #pragma unroll
            for (int nf = 0; nf < 4; ++nf)
                *(float2*)&dst[8*nf + 2*tq] =
                    make_float2(O[m][nf][2*rg] * inv, O[m][nf][2*rg+1] * inv);
        }
}

/* ------------------------------------------------------------------ */
__global__ void __launch_bounds__(256) ln_kernel(
        const float* __restrict__ gamma, const float* __restrict__ beta,
        float* __restrict__ out, float* __restrict__ wout) {
    int row = blockIdx.x, t = threadIdx.x;
    float x = g_ctx[(size_t)row * H + t];
    __shared__ float rs[8], rq[8];
    float s = x, q = x * x;
    #pragma unroll
    for (int o = 16; o; o >>= 1) {
        s += __shfl_xor_sync(0xffffffffu, s, o);
        q += __shfl_xor_sync(0xffffffffu, q, o);
    }
    if ((t & 31) == 0) { rs[t >> 5] = s; rq[t >> 5] = q; }
    __syncthreads();
    float ts = 0.0f, tq = 0.0f;
    #pragma unroll
    for (int i = 0; i < 8; ++i) { ts += rs[i]; tq += rq[i]; }
    float mu = ts * (1.0f / H);
    float var = tq * (1.0f / H) - mu * mu;
    float inv = rsqrtf(var + 1e-5f);
    out[(size_t)row * H + t] = (x - mu) * inv * gamma[t] + beta[t];
    if (t == 0) wout[row] = g_qmask[row] * (1.0f / (float)T);
}

/* ------------------------------------------------------------------ */
extern "C" void kernel_launch(void* const* d_in, const int* in_sizes, int n_in,
                              void* d_out, int out_size) {
    const float* Q  = (const float*)d_in[0];
    const float* K  = (const float*)d_in[1];
    const float* V  = (const float*)d_in[2];
    const float* Wq = (const float*)d_in[3];
    const float* bq = (const float*)d_in[4];
    const float* Wk = (const float*)d_in[5];
    const float* bk = (const float*)d_in[6];
    const float* Wv = (const float*)d_in[7];
    const float* bv = (const float*)d_in[8];
    const float* gamma = (const float*)d_in[9];
    const float* beta  = (const float*)d_in[10];

    float* out  = (float*)d_out;
    float* wout = out + (out_size - Nb * T);

    cudaFuncSetAttribute(attn_kernel,
                         cudaFuncAttributeMaxDynamicSharedMemorySize, SMEM_BYTES);

    mask_kernel<<<dim3(Nb * T, 2), 128>>>(Q, K);
    proj_kernel<<<dim3(H / 64, (Nb * T) / 64, 3), 256>>>(Q, K, V,
                                                         Wq, Wk, Wv,
                                                         bq, bk, bv);
    attn_kernel<<<dim3(T / 128, NH, Nb), 128, SMEM_BYTES>>>();
    ln_kernel<<<Nb * T, 256>>>(gamma, beta, out, wout);
}

// round 17
// speedup vs baseline: 1.1369x; 1.1155x over previous
#include <cuda_runtime.h>
#include <cstdint>
#include <math.h>

#define Nb 2
#define T  2048
#define H  256
#define NH 8
#define D  32
#define SCALE 17.677669529663689f

typedef unsigned long long u64;
typedef uint32_t u32;

__device__ __forceinline__ void fma2(u64& d, u64 a, u64 b) {
    asm("fma.rn.f32x2 %0, %1, %2, %0;" : "+l"(d) : "l"(a), "l"(b));
}
__device__ __forceinline__ u64 pack2(float x, float y) {
    u64 r; asm("mov.b64 %0, {%1, %2};" : "=l"(r) : "f"(x), "f"(y)); return r;
}
__device__ __forceinline__ float2 unpack2(u64 v) {
    float2 f; asm("mov.b64 {%0, %1}, %2;" : "=f"(f.x), "=f"(f.y) : "l"(v)); return f;
}
__device__ __forceinline__ u32 f16pack(float lo, float hi) {
    u32 r; asm("cvt.rn.f16x2.f32 %0, %1, %2;" : "=r"(r) : "f"(hi), "f"(lo)); return r;
}
__device__ __forceinline__ void f16split2(float x, float y, u32& hp, u32& lp) {
    hp = f16pack(x, y);
    float hx, hy;
    asm("{.reg .f16 l,h; mov.b32 {l,h}, %2; cvt.f32.f16 %0, l; cvt.f32.f16 %1, h;}"
        : "=f"(hx), "=f"(hy) : "r"(hp));
    lp = f16pack(x - hx, y - hy);
}
__device__ __forceinline__ u32 smem_u32(const void* p) {
    u32 a;
    asm("{ .reg .u64 t; cvta.to.shared.u64 t, %1; cvt.u32.u64 %0, t; }" : "=r"(a) : "l"(p));
    return a;
}
__device__ __forceinline__ void cpa16(u32 saddr, const void* g) {
    asm volatile("cp.async.cg.shared.global [%0], [%1], 16;" :: "r"(saddr), "l"(g));
}
#define CPA_COMMIT() asm volatile("cp.async.commit_group;" ::: "memory")
#define CPA_WAIT1()  asm volatile("cp.async.wait_group 1;"  ::: "memory")
#define CPA_WAIT0()  asm volatile("cp.async.wait_group 0;"  ::: "memory")
#define MMA16(c, a, b0, b1) \
    asm volatile("mma.sync.aligned.m16n8k16.row.col.f32.f16.f16.f32 " \
        "{%0,%1,%2,%3}, {%4,%5,%6,%7}, {%8,%9}, {%0,%1,%2,%3};" \
        : "+f"((c)[0]), "+f"((c)[1]), "+f"((c)[2]), "+f"((c)[3]) \
        : "r"((a)[0]), "r"((a)[1]), "r"((a)[2]), "r"((a)[3]), "r"(b0), "r"(b1))

__device__ __align__(16) float4 g_Kp[Nb*NH*32*512];
__device__ __align__(16) u64 g_Vp[Nb*NH*32*512];
__device__ __align__(16) float g_Qh[Nb*NH*T*D];
__device__ __align__(16) float g_ctx[Nb*T*H];
__device__ float g_kbias[Nb*T];   /* 0 or -1e35 */
__device__ float g_qmask[Nb*T];

/* ------------------------------------------------------------------ */
/* Mask: warp-per-row. Grid ((Nb*T)/8, 2), 256 thr.                   */
__global__ void __launch_bounds__(256) mask_kernel(
        const float* __restrict__ Q, const float* __restrict__ K) {
    int tid = threadIdx.x, w = tid >> 5, lane = tid & 31;
    int row = blockIdx.x * 8 + w;
    const float* src = (blockIdx.y ? K : Q) + (size_t)row * H + lane * 8;
    float4 a = *(const float4*)src;
    float4 b = *(const float4*)(src + 4);
    float s = fabsf(a.x) + fabsf(a.y) + fabsf(a.z) + fabsf(a.w)
            + fabsf(b.x) + fabsf(b.y) + fabsf(b.z) + fabsf(b.w);
    #pragma unroll
    for (int o = 16; o; o >>= 1) s += __shfl_xor_sync(0xffffffffu, s, o);
    if (lane == 0) {
        if (blockIdx.y) g_kbias[row] = (s != 0.0f) ? 0.0f : -1e35f;
        else            g_qmask[row] = (s != 0.0f) ? 1.0f : 0.0f;
    }
}

/* ------------------------------------------------------------------ */
/* Projection, 128x64 tiles (single wave), pipelined fills.           */
/* dyn smem: Xst[2][32][132] + Wsh[2][32][68] = 51200 B               */
#define XPITCH 132
#define XBUF (32 * XPITCH)          /* 4224 floats */
#define WOFFS (2 * XBUF)            /* 8448 */
#define WBUF (32 * 68)              /* 2176 floats */
#define PROJ_SMEM ((WOFFS + 2 * WBUF) * 4)

__global__ void __launch_bounds__(256) proj_kernel(
        const float* __restrict__ Q, const float* __restrict__ K,
        const float* __restrict__ V,
        const float* __restrict__ Wq, const float* __restrict__ Wk,
        const float* __restrict__ Wv,
        const float* __restrict__ bq, const float* __restrict__ bk,
        const float* __restrict__ bv) {
    extern __shared__ __align__(16) float psm[];
    int sel = blockIdx.z;
    const float* X = (sel == 0) ? Q  : (sel == 1) ? K  : V;
    const float* W = (sel == 0) ? Wq : (sel == 1) ? Wk : Wv;
    const float* b = (sel == 0) ? bq : (sel == 1) ? bk : bv;
    int m0 = blockIdx.y * 128, n0 = blockIdx.x * 64;
    int tid = threadIdx.x, ty = tid >> 4, tx = tid & 15;
    u32 wbase = smem_u32(psm + WOFFS);

    float xr[16];
    u64 acc2[8][2] = {};

    /* prologue */
    #pragma unroll
    for (int i = 0; i < 2; ++i) {
        int idx = tid + i * 256;
        int r2 = idx >> 4, ch = idx & 15;
        cpa16(wbase + (r2 * 68 + ch * 4) * 4, W + r2 * H + n0 + ch * 4);
    }
    CPA_COMMIT();
    #pragma unroll
    for (int it = 0; it < 16; ++it) {
        int e = tid + it * 256;
        xr[it] = X[(m0 + (e >> 5)) * H + (e & 31)];
    }
    #pragma unroll
    for (int it = 0; it < 16; ++it) {
        int e = tid + it * 256;
        psm[(e & 31) * XPITCH + (e >> 5)] = xr[it];
    }

    for (int ksamp = 0; ksamp < 8; ++ksamp) {
        int cur = ksamp & 1;
        CPA_WAIT0();
        __syncthreads();
        if (ksamp < 7) {
            int k1 = (ksamp + 1) * 32;
            #pragma unroll
            for (int i = 0; i < 2; ++i) {
                int idx = tid + i * 256;
                int r2 = idx >> 4, ch = idx & 15;
                cpa16(wbase + ((cur ^ 1) * WBUF + r2 * 68 + ch * 4) * 4,
                      W + (k1 + r2) * H + n0 + ch * 4);
            }
            CPA_COMMIT();
            #pragma unroll
            for (int it = 0; it < 16; ++it) {
                int e = tid + it * 256;
                xr[it] = X[(m0 + (e >> 5)) * H + k1 + (e & 31)];
            }
        }
        const float* Xc = psm + cur * XBUF;
        const float* Wc = psm + WOFFS + cur * WBUF;
        #pragma unroll
        for (int kk = 0; kk < 32; ++kk) {
            float4 a0 = *(const float4*)&Xc[kk * XPITCH + 8 * ty];
            float4 a1 = *(const float4*)&Xc[kk * XPITCH + 8 * ty + 4];
            ulonglong2 bb = *(const ulonglong2*)&Wc[kk * 68 + 4 * tx];
            u64 p;
            p = pack2(a0.x, a0.x); fma2(acc2[0][0], p, bb.x); fma2(acc2[0][1], p, bb.y);
            p = pack2(a0.y, a0.y); fma2(acc2[1][0], p, bb.x); fma2(acc2[1][1], p, bb.y);
            p = pack2(a0.z, a0.z); fma2(acc2[2][0], p, bb.x); fma2(acc2[2][1], p, bb.y);
            p = pack2(a0.w, a0.w); fma2(acc2[3][0], p, bb.x); fma2(acc2[3][1], p, bb.y);
            p = pack2(a1.x, a1.x); fma2(acc2[4][0], p, bb.x); fma2(acc2[4][1], p, bb.y);
            p = pack2(a1.y, a1.y); fma2(acc2[5][0], p, bb.x); fma2(acc2[5][1], p, bb.y);
            p = pack2(a1.z, a1.z); fma2(acc2[6][0], p, bb.x); fma2(acc2[6][1], p, bb.y);
            p = pack2(a1.w, a1.w); fma2(acc2[7][0], p, bb.x); fma2(acc2[7][1], p, bb.y);
        }
        if (ksamp < 7) {
            #pragma unroll
            for (int it = 0; it < 16; ++it) {
                int e = tid + it * 256;
                psm[(cur ^ 1) * XBUF + (e & 31) * XPITCH + (e >> 5)] = xr[it];
            }
        }
    }

    int c0 = n0 + 4 * tx, hh = c0 >> 5, d0 = c0 & 31;
    float b0 = b[c0+0], b1 = b[c0+1], b2 = b[c0+2], b3 = b[c0+3];
    #pragma unroll
    for (int i = 0; i < 8; ++i) {
        int m = m0 + 8 * ty + i, nn = m >> 11, tt = m & 2047;
        float2 lo = unpack2(acc2[i][0]), hi = unpack2(acc2[i][1]);
        float v0 = fmaxf(lo.x + b0, 0.0f), v1 = fmaxf(lo.y + b1, 0.0f);
        float v2 = fmaxf(hi.x + b2, 0.0f), v3 = fmaxf(hi.y + b3, 0.0f);
        int tile = tt >> 6, kk = tt & 63;
        size_t tbase = ((size_t)(nn * NH + hh) * 32 + tile) * 512;
        if (sel == 0) {
            *(float4*)&g_Qh[(((size_t)(nn * NH) + hh) * T + tt) * D + d0] =
                make_float4(v0, v1, v2, v3);
        } else if (sel == 1) {
            u32 h0, l0, h1, l1;
            f16split2(v0, v1, h0, l0);
            f16split2(v2, v3, h1, l1);
            int dp0 = d0 >> 1;
            #pragma unroll
            for (int p = 0; p < 2; ++p) {
                int dp = dp0 + p;
                int ks = dp >> 3, r = dp & 7, sB = r >> 2, tq = r & 3;
                u32* dst = (u32*)&g_Kp[tbase + (4*ks + tq) * 64 + kk];
                dst[sB]     = p ? h1 : h0;
                dst[sB + 2] = p ? l1 : l0;
            }
        } else {
            int kp = kk >> 1, sl = kk & 1;
            int r = kp & 7, sB = r >> 2, tq = r & 3, ks2 = kp >> 3;
            char* base = (char*)&g_Vp[tbase + ((4*ks2 + tq) * 32 + d0)]
                         + sB * 4 + sl * 2;
            unsigned short hv;
            asm("cvt.rn.f16.f32 %0, %1;" : "=h"(hv) : "f"(v0)); *(unsigned short*)(base)      = hv;
            asm("cvt.rn.f16.f32 %0, %1;" : "=h"(hv) : "f"(v1)); *(unsigned short*)(base + 8)  = hv;
            asm("cvt.rn.f16.f32 %0, %1;" : "=h"(hv) : "f"(v2)); *(unsigned short*)(base + 16) = hv;
            asm("cvt.rn.f16.f32 %0, %1;" : "=h"(hv) : "f"(v3)); *(unsigned short*)(base + 24) = hv;
        }
    }
}

/* ------------------------------------------------------------------ */
/* fp16-k16 flash attention: 3-term S, 1-term PV. (unchanged R16)     */
#define KOFF 0
#define VOFF 8448
#define BOFF 13056
#define BUFFB 13312
#define SMEM_BYTES (2 * BUFFB)

__global__ void __launch_bounds__(128, 3) attn_kernel() {
    extern __shared__ __align__(16) char dsm[];
    u32 sb = smem_u32(dsm);

    int tid = threadIdx.x, w = tid >> 5, lane = tid & 31;
    int g = lane >> 2, tq = lane & 3;
    int q0 = blockIdx.x * 128, hh = blockIdx.y, nn = blockIdx.z;
    const float* Qg = g_Qh + (size_t)(nn * NH + hh) * T * D;
    size_t tb = (size_t)(nn * NH + hh) * 32 * 512;

    u32 qh[2][2][4], ql[2][2][4];
    #pragma unroll
    for (int m = 0; m < 2; ++m) {
        int r0 = (q0 + 32 * w + 16 * m + g) * D;
        int r1 = r0 + 8 * D;
        #pragma unroll
        for (int ks = 0; ks < 2; ++ks) {
            float2 xa = *(const float2*)&Qg[r0 + 16*ks + 2*tq];
            float2 xb = *(const float2*)&Qg[r1 + 16*ks + 2*tq];
            float2 xc = *(const float2*)&Qg[r0 + 16*ks + 2*tq + 8];
            float2 xd = *(const float2*)&Qg[r1 + 16*ks + 2*tq + 8];
            f16split2(xa.x, xa.y, qh[m][ks][0], ql[m][ks][0]);
            f16split2(xb.x, xb.y, qh[m][ks][1], ql[m][ks][1]);
            f16split2(xc.x, xc.y, qh[m][ks][2], ql[m][ks][2]);
            f16split2(xd.x, xd.y, qh[m][ks][3], ql[m][ks][3]);
        }
    }
    float O[2][4][4];
    #pragma unroll
    for (int m = 0; m < 2; ++m)
        #pragma unroll
        for (int nf = 0; nf < 4; ++nf)
            #pragma unroll
            for (int c = 0; c < 4; ++c) O[m][nf][c] = 0.0f;
    float mrun[2][2] = {{-1e30f,-1e30f},{-1e30f,-1e30f}};
    float lrun[2][2] = {{0.f,0.f},{0.f,0.f}};

    auto prefetch = [&](int kt, int buf) {
        u32 base = sb + buf * BUFFB;
        const float4* gk = g_Kp + tb + (size_t)kt * 512;
        #pragma unroll
        for (int i = 0; i < 4; ++i) {
            int c = tid + i * 128;
            cpa16(base + KOFF + (c >> 6) * (66*16) + (c & 63) * 16, gk + c);
        }
        const u64* gv = g_Vp + tb + (size_t)kt * 512;
        #pragma unroll
        for (int i = 0; i < 2; ++i) {
            int c = tid + i * 128;
            cpa16(base + VOFF + (c >> 4) * 288 + (c & 15) * 16, gv + c * 2);
        }
        if (tid < 16)
            cpa16(base + BOFF + tid * 16, g_kbias + nn * T + kt * 64 + tid * 4);
        CPA_COMMIT();
    };

    prefetch(0, 0);

    for (int kt = 0; kt < T / 64; ++kt) {
        int cur = kt & 1;
        if (kt < T / 64 - 1) { prefetch(kt + 1, cur ^ 1); CPA_WAIT1(); }
        else CPA_WAIT0();
        __syncthreads();

        const float4* KP4 = (const float4*)(dsm + cur * BUFFB + KOFF);
        const u64*    VPu = (const u64*)   (dsm + cur * BUFFB + VOFF);
        const float*  bias_s = (const float*)(dsm + cur * BUFFB + BOFF);

        float s[2][8][4];
        #pragma unroll
        for (int m = 0; m < 2; ++m)
            #pragma unroll
            for (int j = 0; j < 8; ++j)
                #pragma unroll
                for (int c = 0; c < 4; ++c) s[m][j][c] = 0.0f;
        #pragma unroll
        for (int ks = 0; ks < 2; ++ks) {
            #pragma unroll
            for (int j = 0; j < 8; ++j) {
                float4 kf = KP4[(4*ks + tq) * 66 + 8*j + g];
                u32 bh0 = __float_as_uint(kf.x), bh1 = __float_as_uint(kf.y);
                u32 bl0 = __float_as_uint(kf.z), bl1 = __float_as_uint(kf.w);
                #pragma unroll
                for (int m = 0; m < 2; ++m) {
                    MMA16(s[m][j], qh[m][ks], bh0, bh1);
                    MMA16(s[m][j], ql[m][ks], bh0, bh1);
                    MMA16(s[m][j], qh[m][ks], bl0, bl1);
                }
            }
        }

        float2 bb[8];
        #pragma unroll
        for (int j = 0; j < 8; ++j)
            bb[j] = *(const float2*)&bias_s[8*j + 2*tq];
        #pragma unroll
        for (int m = 0; m < 2; ++m)
            #pragma unroll
            for (int rg = 0; rg < 2; ++rg) {
                float zv[16];
                #pragma unroll
                for (int j = 0; j < 8; ++j) {
                    zv[2*j]   = fmaf(s[m][j][2*rg],   SCALE, bb[j].x);
                    zv[2*j+1] = fmaf(s[m][j][2*rg+1], SCALE, bb[j].y);
                }
                float m0 = fmaxf(zv[0], zv[1]),  m1 = fmaxf(zv[2], zv[3]);
                float m2 = fmaxf(zv[4], zv[5]),  m3 = fmaxf(zv[6], zv[7]);
                float m4 = fmaxf(zv[8], zv[9]),  m5 = fmaxf(zv[10], zv[11]);
                float m6 = fmaxf(zv[12], zv[13]), m7 = fmaxf(zv[14], zv[15]);
                float mx = fmaxf(fmaxf(fmaxf(m0, m1), fmaxf(m2, m3)),
                                 fmaxf(fmaxf(m4, m5), fmaxf(m6, m7)));
                mx = fmaxf(mx, __shfl_xor_sync(0xffffffffu, mx, 1));
                mx = fmaxf(mx, __shfl_xor_sync(0xffffffffu, mx, 2));
                float mn = fmaxf(mrun[m][rg], mx);
                float fr = __expf(mrun[m][rg] - mn);
                mrun[m][rg] = mn;
                float sum = 0.0f;
                #pragma unroll
                for (int j = 0; j < 8; ++j) {
                    float p0 = __expf(zv[2*j]   - mn);
                    float p1 = __expf(zv[2*j+1] - mn);
                    sum += p0 + p1;
                    s[m][j][2*rg] = p0; s[m][j][2*rg+1] = p1;
                }
                sum += __shfl_xor_sync(0xffffffffu, sum, 1);
                sum += __shfl_xor_sync(0xffffffffu, sum, 2);
                lrun[m][rg] = lrun[m][rg] * fr + sum;
                #pragma unroll
                for (int nf = 0; nf < 4; ++nf) {
                    O[m][nf][2*rg]   *= fr;
                    O[m][nf][2*rg+1] *= fr;
                }
            }
        if (kt == T / 64 - 1 && tq == 3) {
            s[0][7][1] = 0.0f; s[0][7][3] = 0.0f;
            s[1][7][1] = 0.0f; s[1][7][3] = 0.0f;
        }

        #pragma unroll
        for (int ks2 = 0; ks2 < 4; ++ks2) {
            u32 ph[2][4];
            #pragma unroll
            for (int m = 0; m < 2; ++m) {
                ph[m][0] = f16pack(s[m][2*ks2][0],   s[m][2*ks2][1]);
                ph[m][1] = f16pack(s[m][2*ks2][2],   s[m][2*ks2][3]);
                ph[m][2] = f16pack(s[m][2*ks2+1][0], s[m][2*ks2+1][1]);
                ph[m][3] = f16pack(s[m][2*ks2+1][2], s[m][2*ks2+1][3]);
            }
            #pragma unroll
            for (int nf = 0; nf < 4; ++nf) {
                u64 vv = VPu[(4*ks2 + tq) * 36 + 8*nf + g];
                u32 v0 = (u32)vv, v1 = (u32)(vv >> 32);
                #pragma unroll
                for (int m = 0; m < 2; ++m)
                    MMA16(O[m][nf], ph[m], v0, v1);
            }
        }
        __syncthreads();
    }

    #pragma unroll
    for (int m = 0; m < 2; ++m)
        #pragma unroll
        for (int rg = 0; rg < 2; ++rg) {
            int row = q0 + 32 * w + 16 * m + 8 * rg + g;
            float inv = g_qmask[nn * T + row] / lrun[m][rg];
            float* dst = &g_ctx[(size_t)(nn * T + row) * H + hh * D];
            #pragma unroll
            for (int nf = 0; nf < 4; ++nf)
                *(float2*)&dst[8*nf + 2*tq] =
                    make_float2(O[m][nf][2*rg] * inv, O[m][nf][2*rg+1] * inv);
        }
}

/* ------------------------------------------------------------------ */
/* LayerNorm: warp-per-row, 8 rows/block. Grid (Nb*T)/8, 256 thr.     */
__global__ void __launch_bounds__(256) ln_kernel(
        const float* __restrict__ gamma, const float* __restrict__ beta,
        float* __restrict__ out, float* __restrict__ wout) {
    __shared__ float gb[2 * H];
    int tid = threadIdx.x;
    gb[tid] = gamma[tid & (H - 1)];          /* tid<256: gamma */
    gb[tid + 256] = beta[tid & (H - 1)];     /* beta */
    __syncthreads();
    int w = tid >> 5, lane = tid & 31;
    int row = blockIdx.x * 8 + w;
    const float* src = g_ctx + (size_t)row * H + lane * 8;
    float4 x0 = *(const float4*)src;
    float4 x1 = *(const float4*)(src + 4);
    float s = x0.x + x0.y + x0.z + x0.w + x1.x + x1.y + x1.z + x1.w;
    float q = x0.x*x0.x + x0.y*x0.y + x0.z*x0.z + x0.w*x0.w
            + x1.x*x1.x + x1.y*x1.y + x1.z*x1.z + x1.w*x1.w;
    #pragma unroll
    for (int o = 16; o; o >>= 1) {
        s += __shfl_xor_sync(0xffffffffu, s, o);
        q += __shfl_xor_sync(0xffffffffu, q, o);
    }
    float mu  = s * (1.0f / H);
    float var = q * (1.0f / H) - mu * mu;
    float inv = rsqrtf(var + 1e-5f);
    const float* ga = gb + lane * 8;
    const float* be = gb + 256 + lane * 8;
    float4 o0, o1;
    o0.x = (x0.x - mu) * inv * ga[0] + be[0];
    o0.y = (x0.y - mu) * inv * ga[1] + be[1];
    o0.z = (x0.z - mu) * inv * ga[2] + be[2];
    o0.w = (x0.w - mu) * inv * ga[3] + be[3];
    o1.x = (x1.x - mu) * inv * ga[4] + be[4];
    o1.y = (x1.y - mu) * inv * ga[5] + be[5];
    o1.z = (x1.z - mu) * inv * ga[6] + be[6];
    o1.w = (x1.w - mu) * inv * ga[7] + be[7];
    float* dst = out + (size_t)row * H + lane * 8;
    *(float4*)dst = o0;
    *(float4*)(dst + 4) = o1;
    if (lane == 0)
        wout[row] = g_qmask[row] * (1.0f / (float)T);
}

/* ------------------------------------------------------------------ */
extern "C" void kernel_launch(void* const* d_in, const int* in_sizes, int n_in,
                              void* d_out, int out_size) {
    const float* Q  = (const float*)d_in[0];
    const float* K  = (const float*)d_in[1];
    const float* V  = (const float*)d_in[2];
    const float* Wq = (const float*)d_in[3];
    const float* bq = (const float*)d_in[4];
    const float* Wk = (const float*)d_in[5];
    const float* bk = (const float*)d_in[6];
    const float* Wv = (const float*)d_in[7];
    const float* bv = (const float*)d_in[8];
    const float* gamma = (const float*)d_in[9];
    const float* beta  = (const float*)d_in[10];

    float* out  = (float*)d_out;
    float* wout = out + (out_size - Nb * T);

    cudaFuncSetAttribute(attn_kernel,
                         cudaFuncAttributeMaxDynamicSharedMemorySize, SMEM_BYTES);
    cudaFuncSetAttribute(proj_kernel,
                         cudaFuncAttributeMaxDynamicSharedMemorySize, PROJ_SMEM);

    mask_kernel<<<dim3((Nb * T) / 8, 2), 256>>>(Q, K);
    proj_kernel<<<dim3(H / 64, (Nb * T) / 128, 3), 256, PROJ_SMEM>>>(
        Q, K, V, Wq, Wk, Wv, bq, bk, bv);
    attn_kernel<<<dim3(T / 128, NH, Nb), 128, SMEM_BYTES>>>();
    ln_kernel<<<(Nb * T) / 8, 256>>>(gamma, beta, out, wout);
}